// round 15
// baseline (speedup 1.0000x reference)
#include <cuda_runtime.h>
#include <cuda_fp16.h>

#define GN        41
#define GNP       44                      // padded z-stride: 44*64B row = 128B-aligned
#define GC        32
#define GF        128
#define PLANE     (GN*GN*GN)              // 68921
#define PLANEPAD  (GN*GN*GNP)             // 73964 cells per copy
#define TOTAL     (PLANE*GC)
#define OFFU      (PLANEPAD*16)           // copy-B offset in uint units
#define OFF4      (PLANEPAD*4)            // copy-B offset in uint4 units

// Smem layout (dynamic): ligH 5120 @0 | wH 8704 @5120 | wS 3072 @13824 |
//                        obuf 33792 @16896  -> total 50688
#define SM_LIG    0
#define SM_WH     5120
#define SM_WS     13824
#define SM_OBUF   16896
#define SM_TOTAL  50688

// Dual-copy transposed fp16 grid, [x][y][z][c] c-innermost, one cell = 64B.
// Copy A: cell (r,z) at r*44+z. Copy B: B[r*44+z-1] = cell (r,z)  (z-shifted),
// so any 4-cell z-span starting at odd z is 128B-aligned in copy B.
__device__ __align__(128) uint4 g4buf[PLANEPAD * 4 * 2];

// ---------------- transpose + fp32->fp16, dual copy (64 cells / block) ----------------
__global__ __launch_bounds__(256) void transpose_kernel(const float* __restrict__ src) {
    __shared__ float tile[32][65];
    const int cellBase = blockIdx.x * 64;
    const int tid = threadIdx.x;
    const int c_l = tid >> 6, cl = tid & 63;
    #pragma unroll
    for (int cc = 0; cc < 8; cc++) {
        const int c = cc * 4 + c_l;
        const int cell = cellBase + cl;
        tile[c][cl] = (cell < PLANE) ? src[c * PLANE + cell] : 0.0f;
    }
    __syncthreads();
    unsigned* g = (unsigned*)g4buf;
    #pragma unroll
    for (int it = 0; it < 4; it++) {
        const int o = it * 256 + tid;
        const int cl2 = o >> 4, u = o & 15;
        const int cell = cellBase + cl2;
        if (cell < PLANE) {
            half2 hh = __floats2half2_rn(tile[2 * u][cl2], tile[2 * u + 1][cl2]);
            const unsigned val = *(unsigned*)&hh;
            const int r = cell / GN, z = cell - r * GN;
            g[(r * GNP + z) * 16 + u] = val;
            if (z >= 1) g[OFFU + (r * GNP + z - 1) * 16 + u] = val;
        }
    }
}

// ---------------- helpers ----------------
__device__ __forceinline__ void bspline(float t, float& w0, float& w1, float& w2, float& w3) {
    float t2 = t * t, t3 = t2 * t;
    const float s = 1.0f / 6.0f;
    w0 = s * (1.0f - 3.0f * t + 3.0f * t2 - t3);
    w1 = s * (4.0f - 6.0f * t2 + 3.0f * t3);
    w2 = s * (1.0f + 3.0f * t + 3.0f * t2 - 3.0f * t3);
    w3 = s * t3;
}
__device__ __forceinline__ int clampi(int v) { return min(max(v, 0), GN - 1); }
__device__ __forceinline__ float normu(float v) {
    float n = 0.5f + 0.5f * (v / 5.0f);
    n = fminf(fmaxf(n, 0.0f), 1.0f);
    return n * (float)(GN - 1);
}
__device__ __forceinline__ half2 shfl_xor_h2(half2 v, int off) {
    unsigned u = *(unsigned*)&v;
    u = __shfl_xor_sync(0xffffffffu, u, off);
    return *(half2*)&u;
}

// ---------------- fused weights + interp + tensor-core encoder ----------------
// Block = 256 threads = 8 warps, 64 points/block, 4 CTAs/SM.
// Phase 0: threads 0..63 compute their point's spline weights (fp16-packed
//          wx/wy/wz + clamped index bytes) -> wS (3 uint4/pt).
// Phase 1: 2 points/warp interp, parity-aligned floor-rate gather, ALL-fp16
//          weighting (HFMA2 y- and x-chains, HMUL2 z-scale), fp16-packed
//          shuffle z-reduce, fp16 -> ligH[64][40].
// Phase 2: mma.sync m16n8k16 + SINGLE-PASS obuf epilogue (dedicated 33KB).
__global__ __launch_bounds__(256, 4) void enc_kernel(
    const float* __restrict__ nb,
    const float* __restrict__ encw,
    const float* __restrict__ encb,
    float* __restrict__ out)
{
    extern __shared__ __align__(128) char smraw[];
    __half* ligH = (__half*)(smraw + SM_LIG);
    __half* wH   = (__half*)(smraw + SM_WH);
    uint4 (*wS)[3] = (uint4(*)[3])(smraw + SM_WS);
    float* obuf  = (float*)(smraw + SM_OBUF);

    const int tid  = threadIdx.x;
    const int warp = tid >> 5;
    const int lane = tid & 31;
    const int p0   = blockIdx.x << 6;

    // Stage enc_w fp16 transposed: wH[k][f] = encw[f*32+k]
    #pragma unroll
    for (int e = tid; e < GF * GC; e += 256) {
        wH[(e & 31) * 136 + (e >> 5)] = __float2half(encw[e]);
    }

    // Per-point spline weights into smem (one thread per point)
    if (tid < 64) {
        const int p = p0 + tid;
        float w[3][4];
        int ib[3];
        #pragma unroll
        for (int d = 0; d < 3; d++) {
            const float u = normu(nb[3 * p + d]);
            const float fb = floorf(u);
            const float t = u - fb;
            ib[d] = (int)fb;
            bspline(t, w[d][0], w[d][1], w[d][2], w[d][3]);
        }
        unsigned ixp = 0, iyp = 0, izp = 0;
        #pragma unroll
        for (int i = 0; i < 4; i++) {
            ixp |= (unsigned)clampi(ib[0] - 1 + i) << (8 * i);
            iyp |= (unsigned)clampi(ib[1] - 1 + i) << (8 * i);
            izp |= (unsigned)clampi(ib[2] - 1 + i) << (8 * i);
        }
        half2 hx01 = __floats2half2_rn(w[0][0], w[0][1]);
        half2 hx23 = __floats2half2_rn(w[0][2], w[0][3]);
        half2 hz01 = __floats2half2_rn(w[2][0], w[2][1]);
        half2 hz23 = __floats2half2_rn(w[2][2], w[2][3]);
        half2 hy01 = __floats2half2_rn(w[1][0], w[1][1]);
        half2 hy23 = __floats2half2_rn(w[1][2], w[1][3]);
        uint4 u0, u1, u2;
        u0.x = *(unsigned*)&hx01; u0.y = *(unsigned*)&hx23;
        u0.z = *(unsigned*)&hz01; u0.w = *(unsigned*)&hz23;
        u1.x = *(unsigned*)&hy01; u1.y = *(unsigned*)&hy23;
        u1.z = ixp; u1.w = iyp;
        u2.x = izp; u2.y = 0; u2.z = 0; u2.w = 0;
        wS[tid][0] = u0; wS[tid][1] = u1; wS[tid][2] = u2;
    }
    __syncthreads();

    // ---- interp: 2 points per warp, parity-aligned gather, all-fp16 math ----
    const int halfp = lane >> 4;
    const int l16   = lane & 15;
    const int zt    = l16 >> 2;
    const int chq   = l16 & 3;
    const uint4* __restrict__ g4 = g4buf;

    #pragma unroll 2
    for (int pr = 0; pr < 4; pr++) {
        const int pp = (warp << 3) + pr * 2 + halfp;

        const uint4 U0 = wS[pp][0];
        const uint4 U1 = wS[pp][1];
        const unsigned izp = wS[pp][2].x;

        const half2 hx01 = *(const half2*)&U0.x;
        const half2 hx23 = *(const half2*)&U0.y;
        const half2 hxb0 = __low2half2(hx01), hxb1 = __high2half2(hx01);
        const half2 hxb2 = __low2half2(hx23), hxb3 = __high2half2(hx23);
        const half2 hy01 = *(const half2*)&U1.x;
        const half2 hy23 = *(const half2*)&U1.y;
        const half2 hyb0 = __low2half2(hy01), hyb1 = __high2half2(hy01);
        const half2 hyb2 = __low2half2(hy23), hyb3 = __high2half2(hy23);
        const unsigned ixp = U1.z, iyp = U1.w;

        const unsigned hzw = (zt & 2) ? U0.w : U0.z;
        const half2 hz2 = *(const half2*)&hzw;
        const half2 hwz = (zt & 1) ? __high2half2(hz2) : __low2half2(hz2);

        const int izv  = (int)((izp >> (8 * zt)) & 255);
        const int zsel = (int)(izp & 1);          // parity of span start (tap0 z)
        const int zq   = (izv - zsel) * 4 + chq + zsel * OFF4;

        int xoff[4], yoff[4];
        #pragma unroll
        for (int i = 0; i < 4; i++) {
            xoff[i] = (int)((ixp >> (8 * i)) & 255) * (GN * GNP * 4);
            yoff[i] = (int)((iyp >> (8 * i)) & 255) * (GNP * 4);
        }

        const half2 hzero = __floats2half2_rn(0.f, 0.f);
        half2 a0 = hzero, a1 = hzero, a2 = hzero, a3 = hzero;

        #pragma unroll
        for (int i = 0; i < 4; i++) {
            half2 j0 = hzero, j1 = hzero, j2 = hzero, j3 = hzero;
            #pragma unroll
            for (int j = 0; j < 4; j++) {
                const uint4 v = __ldg(&g4[xoff[i] + yoff[j] + zq]);
                const half2 hyj = (j == 0) ? hyb0 : (j == 1) ? hyb1 : (j == 2) ? hyb2 : hyb3;
                j0 = __hfma2(hyj, *(const half2*)&v.x, j0);
                j1 = __hfma2(hyj, *(const half2*)&v.y, j1);
                j2 = __hfma2(hyj, *(const half2*)&v.z, j2);
                j3 = __hfma2(hyj, *(const half2*)&v.w, j3);
            }
            const half2 hxi = (i == 0) ? hxb0 : (i == 1) ? hxb1 : (i == 2) ? hxb2 : hxb3;
            a0 = __hfma2(hxi, j0, a0);
            a1 = __hfma2(hxi, j1, a1);
            a2 = __hfma2(hxi, j2, a2);
            a3 = __hfma2(hxi, j3, a3);
        }

        half2 h0 = __hmul2(a0, hwz);
        half2 h1 = __hmul2(a1, hwz);
        half2 h2 = __hmul2(a2, hwz);
        half2 h3 = __hmul2(a3, hwz);

        #pragma unroll
        for (int off = 4; off <= 8; off <<= 1) {
            h0 = __hadd2(h0, shfl_xor_h2(h0, off));
            h1 = __hadd2(h1, shfl_xor_h2(h1, off));
            h2 = __hadd2(h2, shfl_xor_h2(h2, off));
            h3 = __hadd2(h3, shfl_xor_h2(h3, off));
        }

        if (zt == 0) {
            uint4 u;
            u.x = *(unsigned*)&h0; u.y = *(unsigned*)&h1;
            u.z = *(unsigned*)&h2; u.w = *(unsigned*)&h3;
            *(uint4*)&ligH[pp * 40 + chq * 8] = u;
        }
    }
    __syncthreads();

    // ---- tensor-core matmul ----
    const int mt = warp & 3, nt64 = warp >> 2;
    const int r  = lane >> 2;
    const int cq = (lane & 3) * 2;
    const int rbase = mt * 16;
    const int cbase = nt64 * 64;

    float c[8][4];
    #pragma unroll
    for (int nt = 0; nt < 8; nt++) {
        const float2 b2 = __ldg((const float2*)(encb + cbase + nt * 8 + cq));
        c[nt][0] = b2.x; c[nt][1] = b2.y;
        c[nt][2] = b2.x; c[nt][3] = b2.y;
    }

    #pragma unroll
    for (int ks = 0; ks < 2; ks++) {
        const int arow = rbase + (lane & 15);
        const int acol = ks * 16 + ((lane >> 4) << 3);
        unsigned aaddr = (unsigned)__cvta_generic_to_shared(&ligH[arow * 40 + acol]);
        unsigned a0, a1, a2, a3;
        asm volatile("ldmatrix.sync.aligned.m8n8.x4.shared.b16 {%0,%1,%2,%3}, [%4];"
                     : "=r"(a0), "=r"(a1), "=r"(a2), "=r"(a3) : "r"(aaddr));

        #pragma unroll
        for (int nt = 0; nt < 8; nt++) {
            const int brow = ks * 16 + (lane & 15);
            unsigned baddr = (unsigned)__cvta_generic_to_shared(&wH[brow * 136 + cbase + nt * 8]);
            unsigned b0, b1;
            asm volatile("ldmatrix.sync.aligned.m8n8.x2.trans.shared.b16 {%0,%1}, [%2];"
                         : "=r"(b0), "=r"(b1) : "r"(baddr));
            asm volatile("mma.sync.aligned.m16n8k16.row.col.f32.f16.f16.f32 "
                         "{%0,%1,%2,%3}, {%4,%5,%6,%7}, {%8,%9}, {%0,%1,%2,%3};"
                         : "+f"(c[nt][0]), "+f"(c[nt][1]), "+f"(c[nt][2]), "+f"(c[nt][3])
                         : "r"(a0), "r"(a1), "r"(a2), "r"(a3), "r"(b0), "r"(b1));
        }
    }

    // ---- single-pass epilogue: all warps -> 64-row obuf -> coalesced STG ----
    const int rl = rbase + r;
    #pragma unroll
    for (int nt = 0; nt < 8; nt++) {
        const int col = cbase + nt * 8 + cq;
        *(float2*)&obuf[rl * 132 + col]       = make_float2(c[nt][0], c[nt][1]);
        *(float2*)&obuf[(rl + 8) * 132 + col] = make_float2(c[nt][2], c[nt][3]);
    }
    __syncthreads();

    const float4* b4 = (const float4*)obuf;
    float4* o4 = (float4*)out;
    #pragma unroll
    for (int q = 0; q < 8; q++) {
        const int f  = q * 256 + tid;
        const int rr = f >> 5, c4 = f & 31;
        o4[(p0 + rr) * 32 + c4] = b4[rr * 33 + c4];
    }
}

extern "C" void kernel_launch(void* const* d_in, const int* in_sizes, int n_in,
                              void* d_out, int out_size) {
    const float* nb   = nullptr;
    const float* grid = nullptr;
    const float* encw = nullptr;
    const float* encb = nullptr;
    int nbatch = 131072;

    for (int i = 0; i < n_in; i++) {
        switch (in_sizes[i]) {
            case TOTAL:       grid = (const float*)d_in[i]; break;
            case GF * GC:     encw = (const float*)d_in[i]; break;
            case GF:          encb = (const float*)d_in[i]; break;
            default:
                nb = (const float*)d_in[i];
                nbatch = in_sizes[i] / 3;
                break;
        }
    }

    cudaFuncSetAttribute(enc_kernel, cudaFuncAttributeMaxDynamicSharedMemorySize, SM_TOTAL);

    transpose_kernel<<<(PLANE + 63) / 64, 256>>>(grid);
    enc_kernel<<<nbatch / 64, 256, SM_TOTAL>>>(nb, encw, encb, (float*)d_out);
}

// round 16
// speedup vs baseline: 1.1651x; 1.1651x over previous
#include <cuda_runtime.h>
#include <cuda_fp16.h>

#define GN        41
#define GNP       44                      // padded z-stride: 44*64B row = 128B-aligned
#define GC        32
#define GF        128
#define PLANE     (GN*GN*GN)              // 68921
#define PLANEPAD  (GN*GN*GNP)             // 73964 cells per copy
#define TOTAL     (PLANE*GC)
#define OFFU      (PLANEPAD*16)           // copy-B offset in uint units
#define OFF4      (PLANEPAD*4)            // copy-B offset in uint4 units

// Dual-copy transposed fp16 grid, [x][y][z][c] c-innermost, one cell = 64B.
// Copy A: cell (r,z) at r*44+z. Copy B: B[r*44+z-1] = cell (r,z)  (z-shifted),
// so any 4-cell z-span starting at odd z is 128B-aligned in copy B.
__device__ __align__(128) uint4 g4buf[PLANEPAD * 4 * 2];

// ---------------- transpose + fp32->fp16, dual copy (64 cells / block) ----------------
__global__ __launch_bounds__(256) void transpose_kernel(const float* __restrict__ src) {
    __shared__ float tile[32][65];
    const int cellBase = blockIdx.x * 64;
    const int tid = threadIdx.x;
    const int c_l = tid >> 6, cl = tid & 63;
    #pragma unroll
    for (int cc = 0; cc < 8; cc++) {
        const int c = cc * 4 + c_l;
        const int cell = cellBase + cl;
        tile[c][cl] = (cell < PLANE) ? src[c * PLANE + cell] : 0.0f;
    }
    __syncthreads();
    unsigned* g = (unsigned*)g4buf;
    #pragma unroll
    for (int it = 0; it < 4; it++) {
        const int o = it * 256 + tid;
        const int cl2 = o >> 4, u = o & 15;
        const int cell = cellBase + cl2;
        if (cell < PLANE) {
            half2 hh = __floats2half2_rn(tile[2 * u][cl2], tile[2 * u + 1][cl2]);
            const unsigned val = *(unsigned*)&hh;
            const int r = cell / GN, z = cell - r * GN;
            g[(r * GNP + z) * 16 + u] = val;
            if (z >= 1) g[OFFU + (r * GNP + z - 1) * 16 + u] = val;
        }
    }
}

// ---------------- helpers ----------------
__device__ __forceinline__ void bspline(float t, float& w0, float& w1, float& w2, float& w3) {
    float t2 = t * t, t3 = t2 * t;
    const float s = 1.0f / 6.0f;
    w0 = s * (1.0f - 3.0f * t + 3.0f * t2 - t3);
    w1 = s * (4.0f - 6.0f * t2 + 3.0f * t3);
    w2 = s * (1.0f + 3.0f * t + 3.0f * t2 - 3.0f * t3);
    w3 = s * t3;
}
__device__ __forceinline__ int clampi(int v) { return min(max(v, 0), GN - 1); }
__device__ __forceinline__ float normu(float v) {
    float n = 0.5f + 0.5f * (v / 5.0f);
    n = fminf(fmaxf(n, 0.0f), 1.0f);
    return n * (float)(GN - 1);
}
__device__ __forceinline__ half2 shfl_xor_h2(half2 v, int off) {
    unsigned u = *(unsigned*)&v;
    u = __shfl_xor_sync(0xffffffffu, u, off);
    return *(half2*)&u;
}

// ---------------- fused weights + interp + tensor-core encoder ----------------
// Block = 256 threads = 8 warps, 64 points/block, 4 CTAs/SM, 18KB static smem
// (small smem -> big L1D carveout for the gather).
// Phase 0: threads 0..63 compute fp16-packed spline weights -> wS (3 uint4/pt).
// Phase 1: 2 points/warp interp, parity-aligned floor-rate gather, ALL-fp16
//          weighting (HFMA2 y/x chains, HMUL2 z), fp16-packed shuffle z-reduce,
//          fp16 -> ligH[64][40].
// Phase 2: mma.sync m16n8k16 + 2-pass aliased obuf epilogue (proven R12/R14).
__global__ __launch_bounds__(256, 4) void enc_kernel(
    const float* __restrict__ nb,
    const float* __restrict__ encw,
    const float* __restrict__ encb,
    float* __restrict__ out)
{
    __shared__ __align__(16) char smraw[18176];
    __half* ligH = (__half*)smraw;
    __half* wH   = (__half*)(smraw + 5120);
    uint4 (*wS)[3] = (uint4(*)[3])(smraw + 13824);   // 64*48 = 3072B
    float* obuf  = (float*)smraw;                     // epilogue alias

    const int tid  = threadIdx.x;
    const int warp = tid >> 5;
    const int lane = tid & 31;
    const int p0   = blockIdx.x << 6;

    // Stage enc_w fp16 transposed: wH[k][f] = encw[f*32+k]
    #pragma unroll
    for (int e = tid; e < GF * GC; e += 256) {
        wH[(e & 31) * 136 + (e >> 5)] = __float2half(encw[e]);
    }

    // Per-point spline weights into smem (one thread per point)
    if (tid < 64) {
        const int p = p0 + tid;
        float w[3][4];
        int ib[3];
        #pragma unroll
        for (int d = 0; d < 3; d++) {
            const float u = normu(nb[3 * p + d]);
            const float fb = floorf(u);
            const float t = u - fb;
            ib[d] = (int)fb;
            bspline(t, w[d][0], w[d][1], w[d][2], w[d][3]);
        }
        unsigned ixp = 0, iyp = 0, izp = 0;
        #pragma unroll
        for (int i = 0; i < 4; i++) {
            ixp |= (unsigned)clampi(ib[0] - 1 + i) << (8 * i);
            iyp |= (unsigned)clampi(ib[1] - 1 + i) << (8 * i);
            izp |= (unsigned)clampi(ib[2] - 1 + i) << (8 * i);
        }
        half2 hx01 = __floats2half2_rn(w[0][0], w[0][1]);
        half2 hx23 = __floats2half2_rn(w[0][2], w[0][3]);
        half2 hz01 = __floats2half2_rn(w[2][0], w[2][1]);
        half2 hz23 = __floats2half2_rn(w[2][2], w[2][3]);
        half2 hy01 = __floats2half2_rn(w[1][0], w[1][1]);
        half2 hy23 = __floats2half2_rn(w[1][2], w[1][3]);
        uint4 u0, u1, u2;
        u0.x = *(unsigned*)&hx01; u0.y = *(unsigned*)&hx23;
        u0.z = *(unsigned*)&hz01; u0.w = *(unsigned*)&hz23;
        u1.x = *(unsigned*)&hy01; u1.y = *(unsigned*)&hy23;
        u1.z = ixp; u1.w = iyp;
        u2.x = izp; u2.y = 0; u2.z = 0; u2.w = 0;
        wS[tid][0] = u0; wS[tid][1] = u1; wS[tid][2] = u2;
    }
    __syncthreads();

    // ---- interp: 2 points per warp, parity-aligned gather, all-fp16 math ----
    const int halfp = lane >> 4;
    const int l16   = lane & 15;
    const int zt    = l16 >> 2;
    const int chq   = l16 & 3;
    const uint4* __restrict__ g4 = g4buf;

    #pragma unroll 2
    for (int pr = 0; pr < 4; pr++) {
        const int pp = (warp << 3) + pr * 2 + halfp;

        const uint4 U0 = wS[pp][0];
        const uint4 U1 = wS[pp][1];
        const unsigned izp = wS[pp][2].x;

        const half2 hx01 = *(const half2*)&U0.x;
        const half2 hx23 = *(const half2*)&U0.y;
        const half2 hxb0 = __low2half2(hx01), hxb1 = __high2half2(hx01);
        const half2 hxb2 = __low2half2(hx23), hxb3 = __high2half2(hx23);
        const half2 hy01 = *(const half2*)&U1.x;
        const half2 hy23 = *(const half2*)&U1.y;
        const half2 hyb0 = __low2half2(hy01), hyb1 = __high2half2(hy01);
        const half2 hyb2 = __low2half2(hy23), hyb3 = __high2half2(hy23);
        const unsigned ixp = U1.z, iyp = U1.w;

        const unsigned hzw = (zt & 2) ? U0.w : U0.z;
        const half2 hz2 = *(const half2*)&hzw;
        const half2 hwz = (zt & 1) ? __high2half2(hz2) : __low2half2(hz2);

        const int izv  = (int)((izp >> (8 * zt)) & 255);
        const int zsel = (int)(izp & 1);          // parity of span start (tap0 z)
        const int zq   = (izv - zsel) * 4 + chq + zsel * OFF4;

        int xoff[4], yoff[4];
        #pragma unroll
        for (int i = 0; i < 4; i++) {
            xoff[i] = (int)((ixp >> (8 * i)) & 255) * (GN * GNP * 4);
            yoff[i] = (int)((iyp >> (8 * i)) & 255) * (GNP * 4);
        }

        const half2 hzero = __floats2half2_rn(0.f, 0.f);
        half2 a0 = hzero, a1 = hzero, a2 = hzero, a3 = hzero;

        #pragma unroll
        for (int i = 0; i < 4; i++) {
            half2 j0 = hzero, j1 = hzero, j2 = hzero, j3 = hzero;
            #pragma unroll
            for (int j = 0; j < 4; j++) {
                const uint4 v = __ldg(&g4[xoff[i] + yoff[j] + zq]);
                const half2 hyj = (j == 0) ? hyb0 : (j == 1) ? hyb1 : (j == 2) ? hyb2 : hyb3;
                j0 = __hfma2(hyj, *(const half2*)&v.x, j0);
                j1 = __hfma2(hyj, *(const half2*)&v.y, j1);
                j2 = __hfma2(hyj, *(const half2*)&v.z, j2);
                j3 = __hfma2(hyj, *(const half2*)&v.w, j3);
            }
            const half2 hxi = (i == 0) ? hxb0 : (i == 1) ? hxb1 : (i == 2) ? hxb2 : hxb3;
            a0 = __hfma2(hxi, j0, a0);
            a1 = __hfma2(hxi, j1, a1);
            a2 = __hfma2(hxi, j2, a2);
            a3 = __hfma2(hxi, j3, a3);
        }

        half2 h0 = __hmul2(a0, hwz);
        half2 h1 = __hmul2(a1, hwz);
        half2 h2 = __hmul2(a2, hwz);
        half2 h3 = __hmul2(a3, hwz);

        #pragma unroll
        for (int off = 4; off <= 8; off <<= 1) {
            h0 = __hadd2(h0, shfl_xor_h2(h0, off));
            h1 = __hadd2(h1, shfl_xor_h2(h1, off));
            h2 = __hadd2(h2, shfl_xor_h2(h2, off));
            h3 = __hadd2(h3, shfl_xor_h2(h3, off));
        }

        if (zt == 0) {
            uint4 u;
            u.x = *(unsigned*)&h0; u.y = *(unsigned*)&h1;
            u.z = *(unsigned*)&h2; u.w = *(unsigned*)&h3;
            *(uint4*)&ligH[pp * 40 + chq * 8] = u;
        }
    }
    __syncthreads();

    // ---- tensor-core matmul ----
    const int mt = warp & 3, nt64 = warp >> 2;
    const int r  = lane >> 2;
    const int cq = (lane & 3) * 2;
    const int rbase = mt * 16;
    const int cbase = nt64 * 64;

    float c[8][4];
    #pragma unroll
    for (int nt = 0; nt < 8; nt++) {
        const float2 b2 = __ldg((const float2*)(encb + cbase + nt * 8 + cq));
        c[nt][0] = b2.x; c[nt][1] = b2.y;
        c[nt][2] = b2.x; c[nt][3] = b2.y;
    }

    #pragma unroll
    for (int ks = 0; ks < 2; ks++) {
        const int arow = rbase + (lane & 15);
        const int acol = ks * 16 + ((lane >> 4) << 3);
        unsigned aaddr = (unsigned)__cvta_generic_to_shared(&ligH[arow * 40 + acol]);
        unsigned a0, a1, a2, a3;
        asm volatile("ldmatrix.sync.aligned.m8n8.x4.shared.b16 {%0,%1,%2,%3}, [%4];"
                     : "=r"(a0), "=r"(a1), "=r"(a2), "=r"(a3) : "r"(aaddr));

        #pragma unroll
        for (int nt = 0; nt < 8; nt++) {
            const int brow = ks * 16 + (lane & 15);
            unsigned baddr = (unsigned)__cvta_generic_to_shared(&wH[brow * 136 + cbase + nt * 8]);
            unsigned b0, b1;
            asm volatile("ldmatrix.sync.aligned.m8n8.x2.trans.shared.b16 {%0,%1}, [%2];"
                         : "=r"(b0), "=r"(b1) : "r"(baddr));
            asm volatile("mma.sync.aligned.m16n8k16.row.col.f32.f16.f16.f32 "
                         "{%0,%1,%2,%3}, {%4,%5,%6,%7}, {%8,%9}, {%0,%1,%2,%3};"
                         : "+f"(c[nt][0]), "+f"(c[nt][1]), "+f"(c[nt][2]), "+f"(c[nt][3])
                         : "r"(a0), "r"(a1), "r"(a2), "r"(a3), "r"(b0), "r"(b1));
        }
    }
    __syncthreads();   // all mma reads of ligH/wH done; obuf may alias them

    // ---- coalesced epilogue: 2 half-tile passes through smem ----
    #pragma unroll
    for (int h = 0; h < 2; h++) {
        if ((mt >> 1) == h) {
            const int rl = ((mt & 1) << 4) + r;
            #pragma unroll
            for (int nt = 0; nt < 8; nt++) {
                const int col = cbase + nt * 8 + cq;
                *(float2*)&obuf[rl * 132 + col]       = make_float2(c[nt][0], c[nt][1]);
                *(float2*)&obuf[(rl + 8) * 132 + col] = make_float2(c[nt][2], c[nt][3]);
            }
        }
        __syncthreads();
        const float4* b4 = (const float4*)obuf;
        float4* o4 = (float4*)out;
        #pragma unroll
        for (int q = 0; q < 4; q++) {
            const int f  = q * 256 + tid;
            const int rr = f >> 5, c4 = f & 31;
            o4[(p0 + h * 32 + rr) * 32 + c4] = b4[rr * 33 + c4];
        }
        __syncthreads();
    }
}

extern "C" void kernel_launch(void* const* d_in, const int* in_sizes, int n_in,
                              void* d_out, int out_size) {
    const float* nb   = nullptr;
    const float* grid = nullptr;
    const float* encw = nullptr;
    const float* encb = nullptr;
    int nbatch = 131072;

    for (int i = 0; i < n_in; i++) {
        switch (in_sizes[i]) {
            case TOTAL:       grid = (const float*)d_in[i]; break;
            case GF * GC:     encw = (const float*)d_in[i]; break;
            case GF:          encb = (const float*)d_in[i]; break;
            default:
                nb = (const float*)d_in[i];
                nbatch = in_sizes[i] / 3;
                break;
        }
    }

    transpose_kernel<<<(PLANE + 63) / 64, 256>>>(grid);
    enc_kernel<<<nbatch / 64, 256>>>(nb, encw, encb, (float*)d_out);
}

// round 17
// speedup vs baseline: 1.1826x; 1.0151x over previous
#include <cuda_runtime.h>
#include <cuda_fp16.h>

#define GN        41
#define GNP       44                      // padded z-stride: 44*64B row = 128B-aligned
#define GC        32
#define GF        128
#define PLANE     (GN*GN*GN)              // 68921
#define PLANEPAD  (GN*GN*GNP)             // 73964 cells per copy
#define TOTAL     (PLANE*GC)
#define OFFU      (PLANEPAD*16)           // copy-B offset in uint units
#define OFF4      (PLANEPAD*4)            // copy-B offset in uint4 units

// Dual-copy transposed fp16 grid, [x][y][z][c] c-innermost, one cell = 64B.
// Copy A: cell (r,z) at r*44+z. Copy B: B[r*44+z-1] = cell (r,z)  (z-shifted),
// so any 4-cell z-span starting at odd z is 128B-aligned in copy B.
__device__ __align__(128) uint4 g4buf[PLANEPAD * 4 * 2];

// ---------------- transpose + fp32->fp16, dual copy (64 cells / block) ----------------
__global__ __launch_bounds__(256) void transpose_kernel(const float* __restrict__ src) {
    __shared__ float tile[32][65];
    const int cellBase = blockIdx.x * 64;
    const int tid = threadIdx.x;
    const int c_l = tid >> 6, cl = tid & 63;
    #pragma unroll
    for (int cc = 0; cc < 8; cc++) {
        const int c = cc * 4 + c_l;
        const int cell = cellBase + cl;
        tile[c][cl] = (cell < PLANE) ? src[c * PLANE + cell] : 0.0f;
    }
    __syncthreads();
    unsigned* g = (unsigned*)g4buf;
    #pragma unroll
    for (int it = 0; it < 4; it++) {
        const int o = it * 256 + tid;
        const int cl2 = o >> 4, u = o & 15;
        const int cell = cellBase + cl2;
        if (cell < PLANE) {
            half2 hh = __floats2half2_rn(tile[2 * u][cl2], tile[2 * u + 1][cl2]);
            const unsigned val = *(unsigned*)&hh;
            const int r = cell / GN, z = cell - r * GN;
            g[(r * GNP + z) * 16 + u] = val;
            if (z >= 1) g[OFFU + (r * GNP + z - 1) * 16 + u] = val;
        }
    }
}

// ---------------- helpers ----------------
__device__ __forceinline__ void bspline(float t, float& w0, float& w1, float& w2, float& w3) {
    float t2 = t * t, t3 = t2 * t;
    const float s = 1.0f / 6.0f;
    w0 = s * (1.0f - 3.0f * t + 3.0f * t2 - t3);
    w1 = s * (4.0f - 6.0f * t2 + 3.0f * t3);
    w2 = s * (1.0f + 3.0f * t + 3.0f * t2 - 3.0f * t3);
    w3 = s * t3;
}
__device__ __forceinline__ int clampi(int v) { return min(max(v, 0), GN - 1); }
__device__ __forceinline__ float normu(float v) {
    float n = 0.5f + 0.5f * (v / 5.0f);
    n = fminf(fmaxf(n, 0.0f), 1.0f);
    return n * (float)(GN - 1);
}
__device__ __forceinline__ half2 shfl_xor_h2(half2 v, int off) {
    unsigned u = *(unsigned*)&v;
    u = __shfl_xor_sync(0xffffffffu, u, off);
    return *(half2*)&u;
}

// ---------------- fused weights + interp + tensor-core encoder ----------------
// Block = 256 threads = 8 warps, 64 points/block, 4 CTAs/SM, 18KB static smem
// (small smem -> big L1D carveout for the gather).
// Phase 0: threads 0..63 compute fp16-packed spline weights -> wS (3 uint4/pt).
// Phase 1: 2 points/warp interp, parity-aligned floor-rate gather, all-fp16
//          weighting (HFMA2 y/x chains, HMUL2 z), fp16-packed shuffle z-reduce,
//          fp16 -> ligH[64][40].
// Phase 2: mma.sync m16n8k16 + SINGLE-PASS fp16 obuf epilogue (17.4KB alias,
//          2 barriers, halved STS/LDS bytes; final STG fp32).
__global__ __launch_bounds__(256, 4) void enc_kernel(
    const float* __restrict__ nb,
    const float* __restrict__ encw,
    const float* __restrict__ encb,
    float* __restrict__ out)
{
    __shared__ __align__(16) char smraw[18176];
    __half* ligH = (__half*)smraw;
    __half* wH   = (__half*)(smraw + 5120);
    uint4 (*wS)[3] = (uint4(*)[3])(smraw + 13824);   // 64*48 = 3072B
    __half* obufH = (__half*)smraw;                   // epilogue alias: 64*136*2 = 17408B

    const int tid  = threadIdx.x;
    const int warp = tid >> 5;
    const int lane = tid & 31;
    const int p0   = blockIdx.x << 6;

    // Stage enc_w fp16 transposed: wH[k][f] = encw[f*32+k]
    #pragma unroll
    for (int e = tid; e < GF * GC; e += 256) {
        wH[(e & 31) * 136 + (e >> 5)] = __float2half(encw[e]);
    }

    // Per-point spline weights into smem (one thread per point)
    if (tid < 64) {
        const int p = p0 + tid;
        float w[3][4];
        int ib[3];
        #pragma unroll
        for (int d = 0; d < 3; d++) {
            const float u = normu(nb[3 * p + d]);
            const float fb = floorf(u);
            const float t = u - fb;
            ib[d] = (int)fb;
            bspline(t, w[d][0], w[d][1], w[d][2], w[d][3]);
        }
        unsigned ixp = 0, iyp = 0, izp = 0;
        #pragma unroll
        for (int i = 0; i < 4; i++) {
            ixp |= (unsigned)clampi(ib[0] - 1 + i) << (8 * i);
            iyp |= (unsigned)clampi(ib[1] - 1 + i) << (8 * i);
            izp |= (unsigned)clampi(ib[2] - 1 + i) << (8 * i);
        }
        half2 hx01 = __floats2half2_rn(w[0][0], w[0][1]);
        half2 hx23 = __floats2half2_rn(w[0][2], w[0][3]);
        half2 hz01 = __floats2half2_rn(w[2][0], w[2][1]);
        half2 hz23 = __floats2half2_rn(w[2][2], w[2][3]);
        half2 hy01 = __floats2half2_rn(w[1][0], w[1][1]);
        half2 hy23 = __floats2half2_rn(w[1][2], w[1][3]);
        uint4 u0, u1, u2;
        u0.x = *(unsigned*)&hx01; u0.y = *(unsigned*)&hx23;
        u0.z = *(unsigned*)&hz01; u0.w = *(unsigned*)&hz23;
        u1.x = *(unsigned*)&hy01; u1.y = *(unsigned*)&hy23;
        u1.z = ixp; u1.w = iyp;
        u2.x = izp; u2.y = 0; u2.z = 0; u2.w = 0;
        wS[tid][0] = u0; wS[tid][1] = u1; wS[tid][2] = u2;
    }
    __syncthreads();

    // ---- interp: 2 points per warp, parity-aligned gather, all-fp16 math ----
    const int halfp = lane >> 4;
    const int l16   = lane & 15;
    const int zt    = l16 >> 2;
    const int chq   = l16 & 3;
    const uint4* __restrict__ g4 = g4buf;

    #pragma unroll 2
    for (int pr = 0; pr < 4; pr++) {
        const int pp = (warp << 3) + pr * 2 + halfp;

        const uint4 U0 = wS[pp][0];
        const uint4 U1 = wS[pp][1];
        const unsigned izp = wS[pp][2].x;

        const half2 hx01 = *(const half2*)&U0.x;
        const half2 hx23 = *(const half2*)&U0.y;
        const half2 hxb0 = __low2half2(hx01), hxb1 = __high2half2(hx01);
        const half2 hxb2 = __low2half2(hx23), hxb3 = __high2half2(hx23);
        const half2 hy01 = *(const half2*)&U1.x;
        const half2 hy23 = *(const half2*)&U1.y;
        const half2 hyb0 = __low2half2(hy01), hyb1 = __high2half2(hy01);
        const half2 hyb2 = __low2half2(hy23), hyb3 = __high2half2(hy23);
        const unsigned ixp = U1.z, iyp = U1.w;

        const unsigned hzw = (zt & 2) ? U0.w : U0.z;
        const half2 hz2 = *(const half2*)&hzw;
        const half2 hwz = (zt & 1) ? __high2half2(hz2) : __low2half2(hz2);

        const int izv  = (int)((izp >> (8 * zt)) & 255);
        const int zsel = (int)(izp & 1);          // parity of span start (tap0 z)
        const int zq   = (izv - zsel) * 4 + chq + zsel * OFF4;

        int xoff[4], yoff[4];
        #pragma unroll
        for (int i = 0; i < 4; i++) {
            xoff[i] = (int)((ixp >> (8 * i)) & 255) * (GN * GNP * 4);
            yoff[i] = (int)((iyp >> (8 * i)) & 255) * (GNP * 4);
        }

        const half2 hzero = __floats2half2_rn(0.f, 0.f);
        half2 a0 = hzero, a1 = hzero, a2 = hzero, a3 = hzero;

        #pragma unroll
        for (int i = 0; i < 4; i++) {
            half2 j0 = hzero, j1 = hzero, j2 = hzero, j3 = hzero;
            #pragma unroll
            for (int j = 0; j < 4; j++) {
                const uint4 v = __ldg(&g4[xoff[i] + yoff[j] + zq]);
                const half2 hyj = (j == 0) ? hyb0 : (j == 1) ? hyb1 : (j == 2) ? hyb2 : hyb3;
                j0 = __hfma2(hyj, *(const half2*)&v.x, j0);
                j1 = __hfma2(hyj, *(const half2*)&v.y, j1);
                j2 = __hfma2(hyj, *(const half2*)&v.z, j2);
                j3 = __hfma2(hyj, *(const half2*)&v.w, j3);
            }
            const half2 hxi = (i == 0) ? hxb0 : (i == 1) ? hxb1 : (i == 2) ? hxb2 : hxb3;
            a0 = __hfma2(hxi, j0, a0);
            a1 = __hfma2(hxi, j1, a1);
            a2 = __hfma2(hxi, j2, a2);
            a3 = __hfma2(hxi, j3, a3);
        }

        half2 h0 = __hmul2(a0, hwz);
        half2 h1 = __hmul2(a1, hwz);
        half2 h2 = __hmul2(a2, hwz);
        half2 h3 = __hmul2(a3, hwz);

        #pragma unroll
        for (int off = 4; off <= 8; off <<= 1) {
            h0 = __hadd2(h0, shfl_xor_h2(h0, off));
            h1 = __hadd2(h1, shfl_xor_h2(h1, off));
            h2 = __hadd2(h2, shfl_xor_h2(h2, off));
            h3 = __hadd2(h3, shfl_xor_h2(h3, off));
        }

        if (zt == 0) {
            uint4 u;
            u.x = *(unsigned*)&h0; u.y = *(unsigned*)&h1;
            u.z = *(unsigned*)&h2; u.w = *(unsigned*)&h3;
            *(uint4*)&ligH[pp * 40 + chq * 8] = u;
        }
    }
    __syncthreads();

    // ---- tensor-core matmul ----
    const int mt = warp & 3, nt64 = warp >> 2;
    const int r  = lane >> 2;
    const int cq = (lane & 3) * 2;
    const int rbase = mt * 16;
    const int cbase = nt64 * 64;

    float c[8][4];
    #pragma unroll
    for (int nt = 0; nt < 8; nt++) {
        const float2 b2 = __ldg((const float2*)(encb + cbase + nt * 8 + cq));
        c[nt][0] = b2.x; c[nt][1] = b2.y;
        c[nt][2] = b2.x; c[nt][3] = b2.y;
    }

    #pragma unroll
    for (int ks = 0; ks < 2; ks++) {
        const int arow = rbase + (lane & 15);
        const int acol = ks * 16 + ((lane >> 4) << 3);
        unsigned aaddr = (unsigned)__cvta_generic_to_shared(&ligH[arow * 40 + acol]);
        unsigned a0, a1, a2, a3;
        asm volatile("ldmatrix.sync.aligned.m8n8.x4.shared.b16 {%0,%1,%2,%3}, [%4];"
                     : "=r"(a0), "=r"(a1), "=r"(a2), "=r"(a3) : "r"(aaddr));

        #pragma unroll
        for (int nt = 0; nt < 8; nt++) {
            const int brow = ks * 16 + (lane & 15);
            unsigned baddr = (unsigned)__cvta_generic_to_shared(&wH[brow * 136 + cbase + nt * 8]);
            unsigned b0, b1;
            asm volatile("ldmatrix.sync.aligned.m8n8.x2.trans.shared.b16 {%0,%1}, [%2];"
                         : "=r"(b0), "=r"(b1) : "r"(baddr));
            asm volatile("mma.sync.aligned.m16n8k16.row.col.f32.f16.f16.f32 "
                         "{%0,%1,%2,%3}, {%4,%5,%6,%7}, {%8,%9}, {%0,%1,%2,%3};"
                         : "+f"(c[nt][0]), "+f"(c[nt][1]), "+f"(c[nt][2]), "+f"(c[nt][3])
                         : "r"(a0), "r"(a1), "r"(a2), "r"(a3), "r"(b0), "r"(b1));
        }
    }
    __syncthreads();   // all mma reads of ligH/wH done; obufH may alias them

    // ---- single-pass fp16 epilogue: all warps store, one barrier, fp32 STG ----
    const int rl = rbase + r;
    #pragma unroll
    for (int nt = 0; nt < 8; nt++) {
        const int col = cbase + nt * 8 + cq;
        half2 lo = __floats2half2_rn(c[nt][0], c[nt][1]);
        half2 hi = __floats2half2_rn(c[nt][2], c[nt][3]);
        *(half2*)&obufH[rl * 136 + col]       = lo;
        *(half2*)&obufH[(rl + 8) * 136 + col] = hi;
    }
    __syncthreads();

    float4* o4 = (float4*)out;
    #pragma unroll
    for (int q = 0; q < 8; q++) {
        const int f  = q * 256 + tid;
        const int rr = f >> 5, c4 = f & 31;
        const uint2 u = *(const uint2*)&obufH[rr * 136 + c4 * 4];
        const float2 f0 = __half22float2(*(const half2*)&u.x);
        const float2 f1 = __half22float2(*(const half2*)&u.y);
        o4[(p0 + rr) * 32 + c4] = make_float4(f0.x, f0.y, f1.x, f1.y);
    }
}

extern "C" void kernel_launch(void* const* d_in, const int* in_sizes, int n_in,
                              void* d_out, int out_size) {
    const float* nb   = nullptr;
    const float* grid = nullptr;
    const float* encw = nullptr;
    const float* encb = nullptr;
    int nbatch = 131072;

    for (int i = 0; i < n_in; i++) {
        switch (in_sizes[i]) {
            case TOTAL:       grid = (const float*)d_in[i]; break;
            case GF * GC:     encw = (const float*)d_in[i]; break;
            case GF:          encb = (const float*)d_in[i]; break;
            default:
                nb = (const float*)d_in[i];
                nbatch = in_sizes[i] / 3;
                break;
        }
    }

    transpose_kernel<<<(PLANE + 63) / 64, 256>>>(grid);
    enc_kernel<<<nbatch / 64, 256>>>(nb, encw, encb, (float*)d_out);
}